// round 15
// baseline (speedup 1.0000x reference)
#include <cuda_runtime.h>
#include <cuda_bf16.h>
#include <math.h>

// Problem constants (fixed shapes per reference)
#define NN 50000
#define EE 600000
// HID = 128, H = 4, C = 32

// ---------------- scratch (device globals; no allocation allowed) ----------
__device__ float g_h0[NN * 128];     // x @ W_gcn
__device__ float g_h[NN * 128];      // GCN post-ReLU features
__device__ float g_q[NN * 128];
__device__ float g_k[NN * 128];
__device__ float g_v[NN * 128];
__device__ float g_dinv[NN];
__device__ int   g_cnt[NN];          // in-edge count per target (no self loop)
__device__ int   g_row_ptr[NN + 1];  // CSR row pointers (by target)
__device__ int   g_cursor[NN];       // fill cursors
__device__ int   g_esrc[EE];         // source node per edge, grouped by target

// ---------------- f32x2 helpers ---------------------------------------------
__device__ __forceinline__ unsigned long long pack2(float lo, float hi) {
    unsigned long long d;
    asm("mov.b64 %0, {%1, %2};" : "=l"(d) : "f"(lo), "f"(hi));
    return d;
}
__device__ __forceinline__ void unpack2(unsigned long long v, float& lo, float& hi) {
    asm("mov.b64 {%0, %1}, %2;" : "=f"(lo), "=f"(hi) : "l"(v));
}
__device__ __forceinline__ void fma2(unsigned long long& acc, unsigned long long a,
                                     unsigned long long b) {
    asm("fma.rn.f32x2 %0, %1, %2, %0;" : "+l"(acc) : "l"(a), "l"(b));
}

// ---------------- init: zero edge counters -----------------------------------
__global__ void k_zero() {
    int i = blockIdx.x * blockDim.x + threadIdx.x;
    if (i < NN) g_cnt[i] = 0;
}

// ---------------- GEMM: up to 4 weight sets, shared X tile -------------------
__global__ __launch_bounds__(256) void gemm4(
    const float* __restrict__ X,
    const float* __restrict__ W0, const float* __restrict__ b0, float* __restrict__ Y0,
    const float* __restrict__ W1, const float* __restrict__ b1, float* __restrict__ Y1,
    const float* __restrict__ W2, const float* __restrict__ b2, float* __restrict__ Y2,
    const float* __restrict__ W3, const float* __restrict__ b3, float* __restrict__ Y3,
    int n)
{
    extern __shared__ float sm[];
    float* Ws  = sm;               // [k][col] 128*128
    float* XsT = sm + 128 * 128;   // [k][row] 128*128
    const int tid  = threadIdx.x;
    const int lane = tid & 31;
    const int wid  = tid >> 5;
    const int row0 = blockIdx.x * 128;
    const int rbase = wid * 16;

    const float4* X4 = (const float4*)X;
    for (int i = tid; i < 128 * 32; i += 256) {
        int r  = i & 127;
        int c4 = i >> 7;
        int row = row0 + r;
        float4 xv = (row < n) ? X4[row * 32 + c4] : make_float4(0.f, 0.f, 0.f, 0.f);
        XsT[(c4 * 4 + 0) * 128 + r] = xv.x;
        XsT[(c4 * 4 + 1) * 128 + r] = xv.y;
        XsT[(c4 * 4 + 2) * 128 + r] = xv.z;
        XsT[(c4 * 4 + 3) * 128 + r] = xv.w;
    }

    const float* Warr[4] = {W0, W1, W2, W3};
    const float* barr[4] = {b0, b1, b2, b3};
    float*       Yarr[4] = {Y0, Y1, Y2, Y3};

    for (int wsel = 0; wsel < 4; wsel++) {
        const float* W = Warr[wsel];
        if (!W) break;
        __syncthreads();
        {
            float4* Ws4 = (float4*)Ws;
            const float4* W4 = (const float4*)W;
            for (int i = tid; i < 128 * 32; i += 256) Ws4[i] = W4[i];
        }
        __syncthreads();

        unsigned long long acc[8][4];
        #pragma unroll
        for (int rp = 0; rp < 8; rp++)
            #pragma unroll
            for (int c = 0; c < 4; c++) acc[rp][c] = 0ull;

        const float4* Ws4 = (const float4*)Ws;
        #pragma unroll 4
        for (int k = 0; k < 128; k++) {
            float4 wv = Ws4[k * 32 + lane];
            unsigned long long wp0 = pack2(wv.x, wv.x);
            unsigned long long wp1 = pack2(wv.y, wv.y);
            unsigned long long wp2 = pack2(wv.z, wv.z);
            unsigned long long wp3 = pack2(wv.w, wv.w);
            const float* xrow = &XsT[k * 128 + rbase];
            #pragma unroll
            for (int rp = 0; rp < 8; rp++) {
                unsigned long long xx =
                    *reinterpret_cast<const unsigned long long*>(xrow + rp * 2);
                fma2(acc[rp][0], xx, wp0);
                fma2(acc[rp][1], xx, wp1);
                fma2(acc[rp][2], xx, wp2);
                fma2(acc[rp][3], xx, wp3);
            }
        }

        const float* b = barr[wsel];
        float4 bv = b ? ((const float4*)b)[lane] : make_float4(0.f, 0.f, 0.f, 0.f);
        float4* Y4 = (float4*)Yarr[wsel];
        #pragma unroll
        for (int rp = 0; rp < 8; rp++) {
            float lo0, hi0, lo1, hi1, lo2, hi2, lo3, hi3;
            unpack2(acc[rp][0], lo0, hi0);
            unpack2(acc[rp][1], lo1, hi1);
            unpack2(acc[rp][2], lo2, hi2);
            unpack2(acc[rp][3], lo3, hi3);
            int row = row0 + rbase + rp * 2;
            if (row < n) {
                float4 o = make_float4(lo0 + bv.x, lo1 + bv.y, lo2 + bv.z, lo3 + bv.w);
                Y4[row * 32 + lane] = o;
            }
            if (row + 1 < n) {
                float4 o = make_float4(hi0 + bv.x, hi1 + bv.y, hi2 + bv.z, hi3 + bv.w);
                Y4[(row + 1) * 32 + lane] = o;
            }
        }
    }
}

// ---------------- CSR construction -------------------------------------------
__global__ void k_deg(const int* __restrict__ tgt) {
    int e = blockIdx.x * blockDim.x + threadIdx.x;
    if (e < EE) atomicAdd(&g_cnt[tgt[e]], 1);
}

__global__ __launch_bounds__(1024) void k_scan() {
    __shared__ int sums[1024];
    const int tid = threadIdx.x;
    const int CH = (NN + 1023) / 1024;   // 49
    int beg = tid * CH;
    int end = min(beg + CH, NN);
    int s = 0;
    for (int i = beg; i < end; i++) s += g_cnt[i];
    sums[tid] = s;
    __syncthreads();
    for (int off = 1; off < 1024; off <<= 1) {
        int v = 0;
        if (tid >= off) v = sums[tid - off];
        __syncthreads();
        if (tid >= off) sums[tid] += v;
        __syncthreads();
    }
    int run = (tid > 0) ? sums[tid - 1] : 0;
    for (int i = beg; i < end; i++) {
        g_row_ptr[i] = run;
        g_cursor[i]  = run;
        run += g_cnt[i];
    }
    if (tid == 0) g_row_ptr[NN] = EE;
}

__global__ void k_fill(const int* __restrict__ src, const int* __restrict__ tgt) {
    int e = blockIdx.x * blockDim.x + threadIdx.x;
    if (e < EE) {
        int t = tgt[e];
        int pos = atomicAdd(&g_cursor[t], 1);
        g_esrc[pos] = src[e];
    }
}

__global__ void k_dinv() {
    int i = blockIdx.x * blockDim.x + threadIdx.x;
    if (i < NN) g_dinv[i] = rsqrtf((float)(g_cnt[i] + 1));  // +1 self loop
}

// ---------------- GCN aggregate (warp per target, gather, 4x unroll) --------
// h[t] = relu( dinv[t] * sum_s dinv[s]*h0[s]  +  dinv[t]^2 * h0[t] + b )
__global__ __launch_bounds__(256) void k_gcn_agg(const float* __restrict__ b_gcn) {
    int t = (blockIdx.x * blockDim.x + threadIdx.x) >> 5;
    if (t >= NN) return;
    const int lane = threadIdx.x & 31;
    const int beg = g_row_ptr[t];
    const int end = g_row_ptr[t + 1];
    const float4* h04 = (const float4*)g_h0;

    float4 acc = make_float4(0.f, 0.f, 0.f, 0.f);
    for (int base = beg; base < end; base += 32) {
        int nloc = min(32, end - base);
        int sj = (base + lane < end) ? g_esrc[base + lane] : 0;
        float dj = (base + lane < end) ? g_dinv[sj] : 0.f;
        int j = 0;
        for (; j + 4 <= nloc; j += 4) {
            int s0 = __shfl_sync(0xffffffffu, sj, j);
            int s1 = __shfl_sync(0xffffffffu, sj, j + 1);
            int s2 = __shfl_sync(0xffffffffu, sj, j + 2);
            int s3 = __shfl_sync(0xffffffffu, sj, j + 3);
            float d0 = __shfl_sync(0xffffffffu, dj, j);
            float d1 = __shfl_sync(0xffffffffu, dj, j + 1);
            float d2 = __shfl_sync(0xffffffffu, dj, j + 2);
            float d3 = __shfl_sync(0xffffffffu, dj, j + 3);
            float4 h0v = h04[s0 * 32 + lane];
            float4 h1v = h04[s1 * 32 + lane];
            float4 h2v = h04[s2 * 32 + lane];
            float4 h3v = h04[s3 * 32 + lane];
            acc.x = fmaf(d0, h0v.x, acc.x); acc.y = fmaf(d0, h0v.y, acc.y);
            acc.z = fmaf(d0, h0v.z, acc.z); acc.w = fmaf(d0, h0v.w, acc.w);
            acc.x = fmaf(d1, h1v.x, acc.x); acc.y = fmaf(d1, h1v.y, acc.y);
            acc.z = fmaf(d1, h1v.z, acc.z); acc.w = fmaf(d1, h1v.w, acc.w);
            acc.x = fmaf(d2, h2v.x, acc.x); acc.y = fmaf(d2, h2v.y, acc.y);
            acc.z = fmaf(d2, h2v.z, acc.z); acc.w = fmaf(d2, h2v.w, acc.w);
            acc.x = fmaf(d3, h3v.x, acc.x); acc.y = fmaf(d3, h3v.y, acc.y);
            acc.z = fmaf(d3, h3v.z, acc.z); acc.w = fmaf(d3, h3v.w, acc.w);
        }
        for (; j < nloc; j++) {
            int s = __shfl_sync(0xffffffffu, sj, j);
            float ds = __shfl_sync(0xffffffffu, dj, j);
            float4 hv = h04[s * 32 + lane];
            acc.x = fmaf(ds, hv.x, acc.x);
            acc.y = fmaf(ds, hv.y, acc.y);
            acc.z = fmaf(ds, hv.z, acc.z);
            acc.w = fmaf(ds, hv.w, acc.w);
        }
    }
    float dt = g_dinv[t];
    float sw = dt * dt;
    float4 h0v = h04[t * 32 + lane];
    float4 bv = ((const float4*)b_gcn)[lane];
    float4 o;
    o.x = fmaxf(fmaf(acc.x, dt, fmaf(h0v.x, sw, bv.x)), 0.f);
    o.y = fmaxf(fmaf(acc.y, dt, fmaf(h0v.y, sw, bv.y)), 0.f);
    o.z = fmaxf(fmaf(acc.z, dt, fmaf(h0v.z, sw, bv.z)), 0.f);
    o.w = fmaxf(fmaf(acc.w, dt, fmaf(h0v.w, sw, bv.w)), 0.f);
    ((float4*)g_h)[t * 32 + lane] = o;
}

// ---------------- attention (warp per target, gather, 4x unroll) ------------
__global__ __launch_bounds__(256) void k_attn(float* __restrict__ out) {
    int t = (blockIdx.x * blockDim.x + threadIdx.x) >> 5;
    if (t >= NN) return;
    const int lane = threadIdx.x & 31;
    const int beg = g_row_ptr[t];
    const int end = g_row_ptr[t + 1];
    if (beg == end) return;   // no edges: out keeps skip-GEMM value

    const float4* q4 = (const float4*)g_q;
    const float4* k4 = (const float4*)g_k;
    const float4* v4 = (const float4*)g_v;

    float4 qv = q4[t * 32 + lane];
    float4 acc = make_float4(0.f, 0.f, 0.f, 0.f);
    float den = 0.f;
    const float SC = 0.17677669529663687f;   // 1/sqrt(32)

    for (int base = beg; base < end; base += 32) {
        int nloc = min(32, end - base);
        int sj = (base + lane < end) ? g_esrc[base + lane] : 0;
        int j = 0;
        for (; j + 4 <= nloc; j += 4) {
            int s0 = __shfl_sync(0xffffffffu, sj, j);
            int s1 = __shfl_sync(0xffffffffu, sj, j + 1);
            int s2 = __shfl_sync(0xffffffffu, sj, j + 2);
            int s3 = __shfl_sync(0xffffffffu, sj, j + 3);
            float4 k0 = k4[s0 * 32 + lane];
            float4 k1 = k4[s1 * 32 + lane];
            float4 k2 = k4[s2 * 32 + lane];
            float4 k3 = k4[s3 * 32 + lane];
            float4 v0 = v4[s0 * 32 + lane];
            float4 v1 = v4[s1 * 32 + lane];
            float4 v2 = v4[s2 * 32 + lane];
            float4 v3 = v4[s3 * 32 + lane];
            float p0 = qv.x * k0.x + qv.y * k0.y + qv.z * k0.z + qv.w * k0.w;
            float p1 = qv.x * k1.x + qv.y * k1.y + qv.z * k1.z + qv.w * k1.w;
            float p2 = qv.x * k2.x + qv.y * k2.y + qv.z * k2.z + qv.w * k2.w;
            float p3 = qv.x * k3.x + qv.y * k3.y + qv.z * k3.z + qv.w * k3.w;
            p0 += __shfl_xor_sync(0xffffffffu, p0, 1);
            p1 += __shfl_xor_sync(0xffffffffu, p1, 1);
            p2 += __shfl_xor_sync(0xffffffffu, p2, 1);
            p3 += __shfl_xor_sync(0xffffffffu, p3, 1);
            p0 += __shfl_xor_sync(0xffffffffu, p0, 2);
            p1 += __shfl_xor_sync(0xffffffffu, p1, 2);
            p2 += __shfl_xor_sync(0xffffffffu, p2, 2);
            p3 += __shfl_xor_sync(0xffffffffu, p3, 2);
            p0 += __shfl_xor_sync(0xffffffffu, p0, 4);
            p1 += __shfl_xor_sync(0xffffffffu, p1, 4);
            p2 += __shfl_xor_sync(0xffffffffu, p2, 4);
            p3 += __shfl_xor_sync(0xffffffffu, p3, 4);
            float e0 = __expf(p0 * SC);
            float e1 = __expf(p1 * SC);
            float e2 = __expf(p2 * SC);
            float e3 = __expf(p3 * SC);
            acc.x = fmaf(e0, v0.x, acc.x); acc.y = fmaf(e0, v0.y, acc.y);
            acc.z = fmaf(e0, v0.z, acc.z); acc.w = fmaf(e0, v0.w, acc.w);
            acc.x = fmaf(e1, v1.x, acc.x); acc.y = fmaf(e1, v1.y, acc.y);
            acc.z = fmaf(e1, v1.z, acc.z); acc.w = fmaf(e1, v1.w, acc.w);
            acc.x = fmaf(e2, v2.x, acc.x); acc.y = fmaf(e2, v2.y, acc.y);
            acc.z = fmaf(e2, v2.z, acc.z); acc.w = fmaf(e2, v2.w, acc.w);
            acc.x = fmaf(e3, v3.x, acc.x); acc.y = fmaf(e3, v3.y, acc.y);
            acc.z = fmaf(e3, v3.z, acc.z); acc.w = fmaf(e3, v3.w, acc.w);
            den += e0 + e1 + e2 + e3;
        }
        for (; j < nloc; j++) {
            int s = __shfl_sync(0xffffffffu, sj, j);
            float4 kv = k4[s * 32 + lane];
            float4 vv = v4[s * 32 + lane];
            float p = qv.x * kv.x + qv.y * kv.y + qv.z * kv.z + qv.w * kv.w;
            p += __shfl_xor_sync(0xffffffffu, p, 1);
            p += __shfl_xor_sync(0xffffffffu, p, 2);
            p += __shfl_xor_sync(0xffffffffu, p, 4);
            float ea = __expf(p * SC);
            acc.x = fmaf(ea, vv.x, acc.x);
            acc.y = fmaf(ea, vv.y, acc.y);
            acc.z = fmaf(ea, vv.z, acc.z);
            acc.w = fmaf(ea, vv.w, acc.w);
            den += ea;
        }
    }
    float inv = (den > 0.f) ? (1.0f / den) : 0.f;
    float4 o = ((float4*)out)[t * 32 + lane];
    o.x = fmaf(acc.x, inv, o.x);
    o.y = fmaf(acc.y, inv, o.y);
    o.z = fmaf(acc.z, inv, o.z);
    o.w = fmaf(acc.w, inv, o.w);
    ((float4*)out)[t * 32 + lane] = o;
}

// ---------------- launch -----------------------------------------------------
extern "C" void kernel_launch(void* const* d_in, const int* in_sizes, int n_in,
                              void* d_out, int out_size) {
    const float* x  = (const float*)d_in[0];
    const int*   ei = (const int*)d_in[1];
    const int* srcE = ei;        // edge_index[0]
    const int* tgtE = ei + EE;   // edge_index[1]
    const float* Wg = (const float*)d_in[2];
    const float* bg = (const float*)d_in[3];
    const float* Wq = (const float*)d_in[4];
    const float* bq = (const float*)d_in[5];
    const float* Wk = (const float*)d_in[6];
    const float* bk = (const float*)d_in[7];
    const float* Wv = (const float*)d_in[8];
    const float* bv = (const float*)d_in[9];
    const float* Wsk = (const float*)d_in[10];
    const float* bsk = (const float*)d_in[11];
    float* out = (float*)d_out;

    void *p_h0, *p_h, *p_q, *p_k, *p_v;
    cudaGetSymbolAddress(&p_h0, g_h0);
    cudaGetSymbolAddress(&p_h,  g_h);
    cudaGetSymbolAddress(&p_q,  g_q);
    cudaGetSymbolAddress(&p_k,  g_k);
    cudaGetSymbolAddress(&p_v,  g_v);

    const int SMEM = 2 * 128 * 128 * (int)sizeof(float);   // 128KB
    cudaFuncSetAttribute(gemm4, cudaFuncAttributeMaxDynamicSharedMemorySize, SMEM);

    const int TB = 256;
    const int GBLK = (NN + 127) / 128;
    const int NODE_WARP_GRID = (NN * 32 + TB - 1) / TB;

    // CSR build
    k_zero<<<(NN + TB - 1) / TB, TB>>>();
    k_deg<<<(EE + TB - 1) / TB, TB>>>(tgtE);
    k_scan<<<1, 1024>>>();
    k_fill<<<(EE + TB - 1) / TB, TB>>>(srcE, tgtE);
    k_dinv<<<(NN + TB - 1) / TB, TB>>>();
    // h0 = x @ W_gcn
    gemm4<<<GBLK, TB, SMEM>>>(x,
        Wg, nullptr, (float*)p_h0,
        nullptr, nullptr, nullptr,
        nullptr, nullptr, nullptr,
        nullptr, nullptr, nullptr, NN);
    // GCN aggregate + self loop + bias + ReLU (gather, no atomics)
    k_gcn_agg<<<NODE_WARP_GRID, TB>>>(bg);
    // q, k, v, skip projections in one kernel (skip writes straight to out)
    gemm4<<<GBLK, TB, SMEM>>>((const float*)p_h,
        Wq, bq, (float*)p_q,
        Wk, bk, (float*)p_k,
        Wv, bv, (float*)p_v,
        Wsk, bsk, out, NN);
    // attention gather (no atomics)
    k_attn<<<NODE_WARP_GRID, TB>>>(out);
}

// round 16
// speedup vs baseline: 1.1219x; 1.1219x over previous
#include <cuda_runtime.h>
#include <cuda_bf16.h>
#include <math.h>

// Problem constants (fixed shapes per reference)
#define NN 50000
#define EE 600000
// HID = 128, H = 4, C = 32

// ---------------- scratch (device globals; no allocation allowed) ----------
__device__ float g_h0[NN * 128];     // dinv[row] * (x @ W_gcn)   (prescaled)
__device__ float g_h[NN * 128];      // GCN post-ReLU features
__device__ float g_q[NN * 128];
__device__ float g_k[NN * 128];
__device__ float g_v[NN * 128];
__device__ float g_dinv[NN];
__device__ int   g_cnt[NN];          // in-edge count per target (no self loop)
__device__ int   g_row_ptr[NN + 1];  // CSR row pointers (by target)
__device__ int   g_cursor[NN];       // fill cursors
__device__ int   g_esrc[EE];         // source node per edge, grouped by target

// ---------------- f32x2 helpers ---------------------------------------------
__device__ __forceinline__ unsigned long long pack2(float lo, float hi) {
    unsigned long long d;
    asm("mov.b64 %0, {%1, %2};" : "=l"(d) : "f"(lo), "f"(hi));
    return d;
}
__device__ __forceinline__ void unpack2(unsigned long long v, float& lo, float& hi) {
    asm("mov.b64 {%0, %1}, %2;" : "=f"(lo), "=f"(hi) : "l"(v));
}
__device__ __forceinline__ void fma2(unsigned long long& acc, unsigned long long a,
                                     unsigned long long b) {
    asm("fma.rn.f32x2 %0, %1, %2, %0;" : "+l"(acc) : "l"(a), "l"(b));
}

// ---------------- init: zero edge counters -----------------------------------
__global__ void k_zero() {
    int i = blockIdx.x * blockDim.x + threadIdx.x;
    if (i < NN) g_cnt[i] = 0;
}

// ---------------- CSR construction -------------------------------------------
__global__ void k_deg(const int* __restrict__ tgt) {
    int e = blockIdx.x * blockDim.x + threadIdx.x;
    if (e < EE) atomicAdd(&g_cnt[tgt[e]], 1);
}

// One block, 1024 threads. Exclusive scan of g_cnt -> row_ptr, cursor; dinv fused.
__global__ __launch_bounds__(1024) void k_scan() {
    __shared__ int sums[1024];
    const int tid = threadIdx.x;
    const int CH = (NN + 1023) / 1024;   // 49
    int beg = tid * CH;
    int end = min(beg + CH, NN);
    int s = 0;
    for (int i = beg; i < end; i++) s += g_cnt[i];
    sums[tid] = s;
    __syncthreads();
    for (int off = 1; off < 1024; off <<= 1) {
        int v = 0;
        if (tid >= off) v = sums[tid - off];
        __syncthreads();
        if (tid >= off) sums[tid] += v;
        __syncthreads();
    }
    int run = (tid > 0) ? sums[tid - 1] : 0;
    for (int i = beg; i < end; i++) {
        int c = g_cnt[i];
        g_row_ptr[i] = run;
        g_cursor[i]  = run;
        g_dinv[i]    = rsqrtf((float)(c + 1));   // +1 self loop
        run += c;
    }
    if (tid == 0) g_row_ptr[NN] = EE;
}

__global__ void k_fill(const int* __restrict__ src, const int* __restrict__ tgt) {
    int e = blockIdx.x * blockDim.x + threadIdx.x;
    if (e < EE) {
        int t = tgt[e];
        int pos = atomicAdd(&g_cursor[t], 1);
        g_esrc[pos] = src[e];
    }
}

// ---------------- GEMM: up to 4 weight sets, shared X tile -------------------
// Y_j[n,128] = rowscale[row] * (X[n,128] @ W_j[128,128]) + b_j.  f32x2 FMA.
// 64-row x 128-col tile, 96KB smem -> 2 CTAs/SM for latency hiding.
__global__ __launch_bounds__(256) void gemm4(
    const float* __restrict__ X, const float* __restrict__ rowscale,
    const float* __restrict__ W0, const float* __restrict__ b0, float* __restrict__ Y0,
    const float* __restrict__ W1, const float* __restrict__ b1, float* __restrict__ Y1,
    const float* __restrict__ W2, const float* __restrict__ b2, float* __restrict__ Y2,
    const float* __restrict__ W3, const float* __restrict__ b3, float* __restrict__ Y3,
    int n)
{
    extern __shared__ float sm[];
    float* Ws  = sm;               // [k][col] 128*128 (64KB)
    float* XsT = sm + 128 * 128;   // [k][row] 128*64  (32KB)
    const int tid  = threadIdx.x;
    const int lane = tid & 31;
    const int wid  = tid >> 5;
    const int row0 = blockIdx.x * 64;
    const int rbase = wid * 8;     // 8 rows (4 row-pairs) per warp

    const float4* X4 = (const float4*)X;
    for (int i = tid; i < 64 * 32; i += 256) {
        int r  = i & 63;
        int c4 = i >> 6;
        int row = row0 + r;
        float4 xv = (row < n) ? X4[row * 32 + c4] : make_float4(0.f, 0.f, 0.f, 0.f);
        XsT[(c4 * 4 + 0) * 64 + r] = xv.x;
        XsT[(c4 * 4 + 1) * 64 + r] = xv.y;
        XsT[(c4 * 4 + 2) * 64 + r] = xv.z;
        XsT[(c4 * 4 + 3) * 64 + r] = xv.w;
    }

    const float* Warr[4] = {W0, W1, W2, W3};
    const float* barr[4] = {b0, b1, b2, b3};
    float*       Yarr[4] = {Y0, Y1, Y2, Y3};

    for (int wsel = 0; wsel < 4; wsel++) {
        const float* W = Warr[wsel];
        if (!W) break;
        __syncthreads();
        {
            float4* Ws4 = (float4*)Ws;
            const float4* W4 = (const float4*)W;
            for (int i = tid; i < 128 * 32; i += 256) Ws4[i] = W4[i];
        }
        __syncthreads();

        unsigned long long acc[4][4];
        #pragma unroll
        for (int rp = 0; rp < 4; rp++)
            #pragma unroll
            for (int c = 0; c < 4; c++) acc[rp][c] = 0ull;

        const float4* Ws4 = (const float4*)Ws;
        #pragma unroll 4
        for (int k = 0; k < 128; k++) {
            float4 wv = Ws4[k * 32 + lane];
            unsigned long long wp0 = pack2(wv.x, wv.x);
            unsigned long long wp1 = pack2(wv.y, wv.y);
            unsigned long long wp2 = pack2(wv.z, wv.z);
            unsigned long long wp3 = pack2(wv.w, wv.w);
            const float* xrow = &XsT[k * 64 + rbase];
            #pragma unroll
            for (int rp = 0; rp < 4; rp++) {
                unsigned long long xx =
                    *reinterpret_cast<const unsigned long long*>(xrow + rp * 2);
                fma2(acc[rp][0], xx, wp0);
                fma2(acc[rp][1], xx, wp1);
                fma2(acc[rp][2], xx, wp2);
                fma2(acc[rp][3], xx, wp3);
            }
        }

        const float* b = barr[wsel];
        float4 bv = b ? ((const float4*)b)[lane] : make_float4(0.f, 0.f, 0.f, 0.f);
        float4* Y4 = (float4*)Yarr[wsel];
        #pragma unroll
        for (int rp = 0; rp < 4; rp++) {
            float lo0, hi0, lo1, hi1, lo2, hi2, lo3, hi3;
            unpack2(acc[rp][0], lo0, hi0);
            unpack2(acc[rp][1], lo1, hi1);
            unpack2(acc[rp][2], lo2, hi2);
            unpack2(acc[rp][3], lo3, hi3);
            int row = row0 + rbase + rp * 2;
            if (row < n) {
                float sc = rowscale ? rowscale[row] : 1.0f;
                float4 o = make_float4(fmaf(lo0, sc, bv.x), fmaf(lo1, sc, bv.y),
                                       fmaf(lo2, sc, bv.z), fmaf(lo3, sc, bv.w));
                Y4[row * 32 + lane] = o;
            }
            if (row + 1 < n) {
                float sc = rowscale ? rowscale[row + 1] : 1.0f;
                float4 o = make_float4(fmaf(hi0, sc, bv.x), fmaf(hi1, sc, bv.y),
                                       fmaf(hi2, sc, bv.z), fmaf(hi3, sc, bv.w));
                Y4[(row + 1) * 32 + lane] = o;
            }
        }
    }
}

// ---------------- GCN aggregate (warp per target, gather) --------------------
// h0 is prescaled by dinv[s]:  h[t] = relu( dt * (sum_s h0'[s] + h0'[t]) + b )
__global__ __launch_bounds__(256) void k_gcn_agg(const float* __restrict__ b_gcn) {
    int t = (blockIdx.x * blockDim.x + threadIdx.x) >> 5;
    if (t >= NN) return;
    const int lane = threadIdx.x & 31;
    const int beg = g_row_ptr[t];
    const int end = g_row_ptr[t + 1];
    const float4* h04 = (const float4*)g_h0;

    float4 acc = h04[t * 32 + lane];   // self-loop term (already dinv-scaled)
    for (int base = beg; base < end; base += 32) {
        int nloc = min(32, end - base);
        int sj = (base + lane < end) ? g_esrc[base + lane] : 0;
        int j = 0;
        for (; j + 4 <= nloc; j += 4) {
            int s0 = __shfl_sync(0xffffffffu, sj, j);
            int s1 = __shfl_sync(0xffffffffu, sj, j + 1);
            int s2 = __shfl_sync(0xffffffffu, sj, j + 2);
            int s3 = __shfl_sync(0xffffffffu, sj, j + 3);
            float4 h0v = h04[s0 * 32 + lane];
            float4 h1v = h04[s1 * 32 + lane];
            float4 h2v = h04[s2 * 32 + lane];
            float4 h3v = h04[s3 * 32 + lane];
            acc.x += h0v.x + h1v.x + h2v.x + h3v.x;
            acc.y += h0v.y + h1v.y + h2v.y + h3v.y;
            acc.z += h0v.z + h1v.z + h2v.z + h3v.z;
            acc.w += h0v.w + h1v.w + h2v.w + h3v.w;
        }
        for (; j < nloc; j++) {
            int s = __shfl_sync(0xffffffffu, sj, j);
            float4 hv = h04[s * 32 + lane];
            acc.x += hv.x; acc.y += hv.y; acc.z += hv.z; acc.w += hv.w;
        }
    }
    float dt = g_dinv[t];
    float4 bv = ((const float4*)b_gcn)[lane];
    float4 o;
    o.x = fmaxf(fmaf(acc.x, dt, bv.x), 0.f);
    o.y = fmaxf(fmaf(acc.y, dt, bv.y), 0.f);
    o.z = fmaxf(fmaf(acc.z, dt, bv.z), 0.f);
    o.w = fmaxf(fmaf(acc.w, dt, bv.w), 0.f);
    ((float4*)g_h)[t * 32 + lane] = o;
}

// ---------------- attention (warp per target, gather, 4x unroll) ------------
__global__ __launch_bounds__(256) void k_attn(float* __restrict__ out) {
    int t = (blockIdx.x * blockDim.x + threadIdx.x) >> 5;
    if (t >= NN) return;
    const int lane = threadIdx.x & 31;
    const int beg = g_row_ptr[t];
    const int end = g_row_ptr[t + 1];
    if (beg == end) return;   // no edges: out keeps skip-GEMM value

    const float4* q4 = (const float4*)g_q;
    const float4* k4 = (const float4*)g_k;
    const float4* v4 = (const float4*)g_v;

    float4 qv = q4[t * 32 + lane];
    float4 acc = make_float4(0.f, 0.f, 0.f, 0.f);
    float den = 0.f;
    const float SC = 0.17677669529663687f;   // 1/sqrt(32)

    for (int base = beg; base < end; base += 32) {
        int nloc = min(32, end - base);
        int sj = (base + lane < end) ? g_esrc[base + lane] : 0;
        int j = 0;
        for (; j + 4 <= nloc; j += 4) {
            int s0 = __shfl_sync(0xffffffffu, sj, j);
            int s1 = __shfl_sync(0xffffffffu, sj, j + 1);
            int s2 = __shfl_sync(0xffffffffu, sj, j + 2);
            int s3 = __shfl_sync(0xffffffffu, sj, j + 3);
            float4 k0 = k4[s0 * 32 + lane];
            float4 k1 = k4[s1 * 32 + lane];
            float4 k2 = k4[s2 * 32 + lane];
            float4 k3 = k4[s3 * 32 + lane];
            float p0 = qv.x * k0.x + qv.y * k0.y + qv.z * k0.z + qv.w * k0.w;
            float p1 = qv.x * k1.x + qv.y * k1.y + qv.z * k1.z + qv.w * k1.w;
            float p2 = qv.x * k2.x + qv.y * k2.y + qv.z * k2.z + qv.w * k2.w;
            float p3 = qv.x * k3.x + qv.y * k3.y + qv.z * k3.z + qv.w * k3.w;
            float4 v0 = v4[s0 * 32 + lane];
            float4 v1 = v4[s1 * 32 + lane];
            float4 v2 = v4[s2 * 32 + lane];
            float4 v3 = v4[s3 * 32 + lane];
            p0 += __shfl_xor_sync(0xffffffffu, p0, 1);
            p1 += __shfl_xor_sync(0xffffffffu, p1, 1);
            p2 += __shfl_xor_sync(0xffffffffu, p2, 1);
            p3 += __shfl_xor_sync(0xffffffffu, p3, 1);
            p0 += __shfl_xor_sync(0xffffffffu, p0, 2);
            p1 += __shfl_xor_sync(0xffffffffu, p1, 2);
            p2 += __shfl_xor_sync(0xffffffffu, p2, 2);
            p3 += __shfl_xor_sync(0xffffffffu, p3, 2);
            p0 += __shfl_xor_sync(0xffffffffu, p0, 4);
            p1 += __shfl_xor_sync(0xffffffffu, p1, 4);
            p2 += __shfl_xor_sync(0xffffffffu, p2, 4);
            p3 += __shfl_xor_sync(0xffffffffu, p3, 4);
            float e0 = __expf(p0 * SC);
            float e1 = __expf(p1 * SC);
            float e2 = __expf(p2 * SC);
            float e3 = __expf(p3 * SC);
            acc.x = fmaf(e0, v0.x, acc.x); acc.y = fmaf(e0, v0.y, acc.y);
            acc.z = fmaf(e0, v0.z, acc.z); acc.w = fmaf(e0, v0.w, acc.w);
            acc.x = fmaf(e1, v1.x, acc.x); acc.y = fmaf(e1, v1.y, acc.y);
            acc.z = fmaf(e1, v1.z, acc.z); acc.w = fmaf(e1, v1.w, acc.w);
            acc.x = fmaf(e2, v2.x, acc.x); acc.y = fmaf(e2, v2.y, acc.y);
            acc.z = fmaf(e2, v2.z, acc.z); acc.w = fmaf(e2, v2.w, acc.w);
            acc.x = fmaf(e3, v3.x, acc.x); acc.y = fmaf(e3, v3.y, acc.y);
            acc.z = fmaf(e3, v3.z, acc.z); acc.w = fmaf(e3, v3.w, acc.w);
            den += e0 + e1 + e2 + e3;
        }
        for (; j < nloc; j++) {
            int s = __shfl_sync(0xffffffffu, sj, j);
            float4 kv = k4[s * 32 + lane];
            float4 vv = v4[s * 32 + lane];
            float p = qv.x * kv.x + qv.y * kv.y + qv.z * kv.z + qv.w * kv.w;
            p += __shfl_xor_sync(0xffffffffu, p, 1);
            p += __shfl_xor_sync(0xffffffffu, p, 2);
            p += __shfl_xor_sync(0xffffffffu, p, 4);
            float ea = __expf(p * SC);
            acc.x = fmaf(ea, vv.x, acc.x);
            acc.y = fmaf(ea, vv.y, acc.y);
            acc.z = fmaf(ea, vv.z, acc.z);
            acc.w = fmaf(ea, vv.w, acc.w);
            den += ea;
        }
    }
    float inv = (den > 0.f) ? (1.0f / den) : 0.f;
    float4 o = ((float4*)out)[t * 32 + lane];
    o.x = fmaf(acc.x, inv, o.x);
    o.y = fmaf(acc.y, inv, o.y);
    o.z = fmaf(acc.z, inv, o.z);
    o.w = fmaf(acc.w, inv, o.w);
    ((float4*)out)[t * 32 + lane] = o;
}

// ---------------- launch -----------------------------------------------------
extern "C" void kernel_launch(void* const* d_in, const int* in_sizes, int n_in,
                              void* d_out, int out_size) {
    const float* x  = (const float*)d_in[0];
    const int*   ei = (const int*)d_in[1];
    const int* srcE = ei;        // edge_index[0]
    const int* tgtE = ei + EE;   // edge_index[1]
    const float* Wg = (const float*)d_in[2];
    const float* bg = (const float*)d_in[3];
    const float* Wq = (const float*)d_in[4];
    const float* bq = (const float*)d_in[5];
    const float* Wk = (const float*)d_in[6];
    const float* bk = (const float*)d_in[7];
    const float* Wv = (const float*)d_in[8];
    const float* bv = (const float*)d_in[9];
    const float* Wsk = (const float*)d_in[10];
    const float* bsk = (const float*)d_in[11];
    float* out = (float*)d_out;

    void *p_h0, *p_h, *p_q, *p_k, *p_v, *p_dinv;
    cudaGetSymbolAddress(&p_h0, g_h0);
    cudaGetSymbolAddress(&p_h,  g_h);
    cudaGetSymbolAddress(&p_q,  g_q);
    cudaGetSymbolAddress(&p_k,  g_k);
    cudaGetSymbolAddress(&p_v,  g_v);
    cudaGetSymbolAddress(&p_dinv, g_dinv);

    const int SMEM = (128 * 128 + 128 * 64) * (int)sizeof(float);   // 96KB
    cudaFuncSetAttribute(gemm4, cudaFuncAttributeMaxDynamicSharedMemorySize, SMEM);

    const int TB = 256;
    const int GBLK = (NN + 63) / 64;
    const int NODE_WARP_GRID = (NN * 32 + TB - 1) / TB;

    // CSR build first (dinv needed by the h0 GEMM epilogue)
    k_zero<<<(NN + TB - 1) / TB, TB>>>();                       // 1
    k_deg<<<(EE + TB - 1) / TB, TB>>>(tgtE);                    // 2
    k_scan<<<1, 1024>>>();                                      // 3 (+dinv)
    k_fill<<<(EE + TB - 1) / TB, TB>>>(srcE, tgtE);             // 4
    // h0' = dinv * (x @ W_gcn)
    gemm4<<<GBLK, TB, SMEM>>>(x, (const float*)p_dinv,          // 5
        Wg, nullptr, (float*)p_h0,
        nullptr, nullptr, nullptr,
        nullptr, nullptr, nullptr,
        nullptr, nullptr, nullptr, NN);
    // GCN aggregate + self loop + bias + ReLU (gather, no atomics)  -- launch #6 (profiled)
    k_gcn_agg<<<NODE_WARP_GRID, TB>>>(bg);                      // 6
    // q, k, v, skip projections in one kernel (skip writes straight to out)
    gemm4<<<GBLK, TB, SMEM>>>((const float*)p_h, nullptr,       // 7
        Wq, bq, (float*)p_q,
        Wk, bk, (float*)p_k,
        Wv, bv, (float*)p_v,
        Wsk, bsk, out, NN);
    // attention gather (no atomics)
    k_attn<<<NODE_WARP_GRID, TB>>>(out);                        // 8
}

// round 17
// speedup vs baseline: 1.1292x; 1.0065x over previous
#include <cuda_runtime.h>
#include <cuda_bf16.h>
#include <math.h>

// Problem constants (fixed shapes per reference)
#define NN 50000
#define EE 600000
// HID = 128, H = 4, C = 32

// ---------------- scratch (device globals; no allocation allowed) ----------
__device__ float g_h0[NN * 128];     // dinv[row] * (x @ W_gcn)   (prescaled)
__device__ float g_h[NN * 128];      // GCN post-ReLU features
__device__ float g_q[NN * 128];
__device__ float g_k[NN * 128];
__device__ float g_v[NN * 128];
__device__ float g_dinv[NN];
__device__ int   g_cnt[NN];          // in-edge count per target (no self loop)
__device__ int   g_row_ptr[NN + 1];  // CSR row pointers (by target)
__device__ int   g_cursor[NN];       // fill cursors
__device__ int   g_esrc[EE];         // source node per edge, grouped by target

// ---------------- f32x2 helpers ---------------------------------------------
__device__ __forceinline__ unsigned long long pack2(float lo, float hi) {
    unsigned long long d;
    asm("mov.b64 %0, {%1, %2};" : "=l"(d) : "f"(lo), "f"(hi));
    return d;
}
__device__ __forceinline__ void unpack2(unsigned long long v, float& lo, float& hi) {
    asm("mov.b64 {%0, %1}, %2;" : "=f"(lo), "=f"(hi) : "l"(v));
}
__device__ __forceinline__ void fma2(unsigned long long& acc, unsigned long long a,
                                     unsigned long long b) {
    asm("fma.rn.f32x2 %0, %1, %2, %0;" : "+l"(acc) : "l"(a), "l"(b));
}

// ---------------- init: zero edge counters -----------------------------------
__global__ void k_zero() {
    int i = blockIdx.x * blockDim.x + threadIdx.x;
    if (i < NN) g_cnt[i] = 0;
}

// ---------------- CSR construction -------------------------------------------
__global__ void k_deg(const int* __restrict__ tgt) {
    int e = blockIdx.x * blockDim.x + threadIdx.x;
    if (e < EE) atomicAdd(&g_cnt[tgt[e]], 1);
}

// One block, 1024 threads. Exclusive scan of g_cnt -> row_ptr, cursor; dinv fused.
__global__ __launch_bounds__(1024) void k_scan() {
    __shared__ int sums[1024];
    const int tid = threadIdx.x;
    const int CH = (NN + 1023) / 1024;   // 49
    int beg = tid * CH;
    int end = min(beg + CH, NN);
    int s = 0;
    for (int i = beg; i < end; i++) s += g_cnt[i];
    sums[tid] = s;
    __syncthreads();
    for (int off = 1; off < 1024; off <<= 1) {
        int v = 0;
        if (tid >= off) v = sums[tid - off];
        __syncthreads();
        if (tid >= off) sums[tid] += v;
        __syncthreads();
    }
    int run = (tid > 0) ? sums[tid - 1] : 0;
    for (int i = beg; i < end; i++) {
        int c = g_cnt[i];
        g_row_ptr[i] = run;
        g_cursor[i]  = run;
        g_dinv[i]    = rsqrtf((float)(c + 1));   // +1 self loop
        run += c;
    }
    if (tid == 0) g_row_ptr[NN] = EE;
}

__global__ void k_fill(const int* __restrict__ src, const int* __restrict__ tgt) {
    int e = blockIdx.x * blockDim.x + threadIdx.x;
    if (e < EE) {
        int t = tgt[e];
        int pos = atomicAdd(&g_cursor[t], 1);
        g_esrc[pos] = src[e];
    }
}

// ---------------- GEMM: up to 4 weight sets, shared X tile -------------------
// Y_j[n,128] = rowscale[row] * (X[n,128] @ W_j[128,128]) + b_j.  f32x2 FMA.
// 64-row x 128-col tile, 96KB smem -> 2 CTAs/SM for latency hiding.
__global__ __launch_bounds__(256) void gemm4(
    const float* __restrict__ X, const float* __restrict__ rowscale,
    const float* __restrict__ W0, const float* __restrict__ b0, float* __restrict__ Y0,
    const float* __restrict__ W1, const float* __restrict__ b1, float* __restrict__ Y1,
    const float* __restrict__ W2, const float* __restrict__ b2, float* __restrict__ Y2,
    const float* __restrict__ W3, const float* __restrict__ b3, float* __restrict__ Y3,
    int n)
{
    extern __shared__ float sm[];
    float* Ws  = sm;               // [k][col] 128*128 (64KB)
    float* XsT = sm + 128 * 128;   // [k][row] 128*64  (32KB)
    const int tid  = threadIdx.x;
    const int lane = tid & 31;
    const int wid  = tid >> 5;
    const int row0 = blockIdx.x * 64;
    const int rbase = wid * 8;     // 8 rows (4 row-pairs) per warp

    const float4* X4 = (const float4*)X;
    for (int i = tid; i < 64 * 32; i += 256) {
        int r  = i & 63;
        int c4 = i >> 6;
        int row = row0 + r;
        float4 xv = (row < n) ? X4[row * 32 + c4] : make_float4(0.f, 0.f, 0.f, 0.f);
        XsT[(c4 * 4 + 0) * 64 + r] = xv.x;
        XsT[(c4 * 4 + 1) * 64 + r] = xv.y;
        XsT[(c4 * 4 + 2) * 64 + r] = xv.z;
        XsT[(c4 * 4 + 3) * 64 + r] = xv.w;
    }

    const float* Warr[4] = {W0, W1, W2, W3};
    const float* barr[4] = {b0, b1, b2, b3};
    float*       Yarr[4] = {Y0, Y1, Y2, Y3};

    for (int wsel = 0; wsel < 4; wsel++) {
        const float* W = Warr[wsel];
        if (!W) break;
        __syncthreads();
        {
            float4* Ws4 = (float4*)Ws;
            const float4* W4 = (const float4*)W;
            for (int i = tid; i < 128 * 32; i += 256) Ws4[i] = W4[i];
        }
        __syncthreads();

        unsigned long long acc[4][4];
        #pragma unroll
        for (int rp = 0; rp < 4; rp++)
            #pragma unroll
            for (int c = 0; c < 4; c++) acc[rp][c] = 0ull;

        const float4* Ws4 = (const float4*)Ws;
        #pragma unroll 4
        for (int k = 0; k < 128; k++) {
            float4 wv = Ws4[k * 32 + lane];
            unsigned long long wp0 = pack2(wv.x, wv.x);
            unsigned long long wp1 = pack2(wv.y, wv.y);
            unsigned long long wp2 = pack2(wv.z, wv.z);
            unsigned long long wp3 = pack2(wv.w, wv.w);
            const float* xrow = &XsT[k * 64 + rbase];
            #pragma unroll
            for (int rp = 0; rp < 4; rp++) {
                unsigned long long xx =
                    *reinterpret_cast<const unsigned long long*>(xrow + rp * 2);
                fma2(acc[rp][0], xx, wp0);
                fma2(acc[rp][1], xx, wp1);
                fma2(acc[rp][2], xx, wp2);
                fma2(acc[rp][3], xx, wp3);
            }
        }

        const float* b = barr[wsel];
        float4 bv = b ? ((const float4*)b)[lane] : make_float4(0.f, 0.f, 0.f, 0.f);
        float4* Y4 = (float4*)Yarr[wsel];
        #pragma unroll
        for (int rp = 0; rp < 4; rp++) {
            float lo0, hi0, lo1, hi1, lo2, hi2, lo3, hi3;
            unpack2(acc[rp][0], lo0, hi0);
            unpack2(acc[rp][1], lo1, hi1);
            unpack2(acc[rp][2], lo2, hi2);
            unpack2(acc[rp][3], lo3, hi3);
            int row = row0 + rbase + rp * 2;
            if (row < n) {
                float sc = rowscale ? rowscale[row] : 1.0f;
                float4 o = make_float4(fmaf(lo0, sc, bv.x), fmaf(lo1, sc, bv.y),
                                       fmaf(lo2, sc, bv.z), fmaf(lo3, sc, bv.w));
                Y4[row * 32 + lane] = o;
            }
            if (row + 1 < n) {
                float sc = rowscale ? rowscale[row + 1] : 1.0f;
                float4 o = make_float4(fmaf(hi0, sc, bv.x), fmaf(hi1, sc, bv.y),
                                       fmaf(hi2, sc, bv.z), fmaf(hi3, sc, bv.w));
                Y4[(row + 1) * 32 + lane] = o;
            }
        }
    }
}

// ---------------- GCN aggregate (warp per target, gather) --------------------
// h0 is prescaled by dinv[s]:  h[t] = relu( dt * (sum_s h0'[s] + h0'[t]) + b )
__global__ __launch_bounds__(256) void k_gcn_agg(const float* __restrict__ b_gcn) {
    int t = (blockIdx.x * blockDim.x + threadIdx.x) >> 5;
    if (t >= NN) return;
    const int lane = threadIdx.x & 31;
    const int beg = g_row_ptr[t];
    const int end = g_row_ptr[t + 1];
    const float4* h04 = (const float4*)g_h0;

    float4 acc = h04[t * 32 + lane];   // self-loop term (already dinv-scaled)
    for (int base = beg; base < end; base += 32) {
        int nloc = min(32, end - base);
        int sj = (base + lane < end) ? g_esrc[base + lane] : 0;
        int j = 0;
        for (; j + 4 <= nloc; j += 4) {
            int s0 = __shfl_sync(0xffffffffu, sj, j);
            int s1 = __shfl_sync(0xffffffffu, sj, j + 1);
            int s2 = __shfl_sync(0xffffffffu, sj, j + 2);
            int s3 = __shfl_sync(0xffffffffu, sj, j + 3);
            float4 h0v = h04[s0 * 32 + lane];
            float4 h1v = h04[s1 * 32 + lane];
            float4 h2v = h04[s2 * 32 + lane];
            float4 h3v = h04[s3 * 32 + lane];
            acc.x += h0v.x + h1v.x + h2v.x + h3v.x;
            acc.y += h0v.y + h1v.y + h2v.y + h3v.y;
            acc.z += h0v.z + h1v.z + h2v.z + h3v.z;
            acc.w += h0v.w + h1v.w + h2v.w + h3v.w;
        }
        for (; j < nloc; j++) {
            int s = __shfl_sync(0xffffffffu, sj, j);
            float4 hv = h04[s * 32 + lane];
            acc.x += hv.x; acc.y += hv.y; acc.z += hv.z; acc.w += hv.w;
        }
    }
    float dt = g_dinv[t];
    float4 bv = ((const float4*)b_gcn)[lane];
    float4 o;
    o.x = fmaxf(fmaf(acc.x, dt, bv.x), 0.f);
    o.y = fmaxf(fmaf(acc.y, dt, bv.y), 0.f);
    o.z = fmaxf(fmaf(acc.z, dt, bv.z), 0.f);
    o.w = fmaxf(fmaf(acc.w, dt, bv.w), 0.f);
    ((float4*)g_h)[t * 32 + lane] = o;
}

// ---------------- attention (warp per target, gather, 4x unroll) ------------
__global__ __launch_bounds__(256) void k_attn(float* __restrict__ out) {
    int t = (blockIdx.x * blockDim.x + threadIdx.x) >> 5;
    if (t >= NN) return;
    const int lane = threadIdx.x & 31;
    const int beg = g_row_ptr[t];
    const int end = g_row_ptr[t + 1];
    if (beg == end) return;   // no edges: out keeps skip-GEMM value

    const float4* q4 = (const float4*)g_q;
    const float4* k4 = (const float4*)g_k;
    const float4* v4 = (const float4*)g_v;

    float4 qv = q4[t * 32 + lane];
    float4 acc = make_float4(0.f, 0.f, 0.f, 0.f);
    float den = 0.f;
    const float SC = 0.17677669529663687f;   // 1/sqrt(32)

    for (int base = beg; base < end; base += 32) {
        int nloc = min(32, end - base);
        int sj = (base + lane < end) ? g_esrc[base + lane] : 0;
        int j = 0;
        for (; j + 4 <= nloc; j += 4) {
            int s0 = __shfl_sync(0xffffffffu, sj, j);
            int s1 = __shfl_sync(0xffffffffu, sj, j + 1);
            int s2 = __shfl_sync(0xffffffffu, sj, j + 2);
            int s3 = __shfl_sync(0xffffffffu, sj, j + 3);
            float4 k0 = k4[s0 * 32 + lane];
            float4 k1 = k4[s1 * 32 + lane];
            float4 k2 = k4[s2 * 32 + lane];
            float4 k3 = k4[s3 * 32 + lane];
            float p0 = qv.x * k0.x + qv.y * k0.y + qv.z * k0.z + qv.w * k0.w;
            float p1 = qv.x * k1.x + qv.y * k1.y + qv.z * k1.z + qv.w * k1.w;
            float p2 = qv.x * k2.x + qv.y * k2.y + qv.z * k2.z + qv.w * k2.w;
            float p3 = qv.x * k3.x + qv.y * k3.y + qv.z * k3.z + qv.w * k3.w;
            float4 v0 = v4[s0 * 32 + lane];
            float4 v1 = v4[s1 * 32 + lane];
            float4 v2 = v4[s2 * 32 + lane];
            float4 v3 = v4[s3 * 32 + lane];
            p0 += __shfl_xor_sync(0xffffffffu, p0, 1);
            p1 += __shfl_xor_sync(0xffffffffu, p1, 1);
            p2 += __shfl_xor_sync(0xffffffffu, p2, 1);
            p3 += __shfl_xor_sync(0xffffffffu, p3, 1);
            p0 += __shfl_xor_sync(0xffffffffu, p0, 2);
            p1 += __shfl_xor_sync(0xffffffffu, p1, 2);
            p2 += __shfl_xor_sync(0xffffffffu, p2, 2);
            p3 += __shfl_xor_sync(0xffffffffu, p3, 2);
            p0 += __shfl_xor_sync(0xffffffffu, p0, 4);
            p1 += __shfl_xor_sync(0xffffffffu, p1, 4);
            p2 += __shfl_xor_sync(0xffffffffu, p2, 4);
            p3 += __shfl_xor_sync(0xffffffffu, p3, 4);
            float e0 = __expf(p0 * SC);
            float e1 = __expf(p1 * SC);
            float e2 = __expf(p2 * SC);
            float e3 = __expf(p3 * SC);
            acc.x = fmaf(e0, v0.x, acc.x); acc.y = fmaf(e0, v0.y, acc.y);
            acc.z = fmaf(e0, v0.z, acc.z); acc.w = fmaf(e0, v0.w, acc.w);
            acc.x = fmaf(e1, v1.x, acc.x); acc.y = fmaf(e1, v1.y, acc.y);
            acc.z = fmaf(e1, v1.z, acc.z); acc.w = fmaf(e1, v1.w, acc.w);
            acc.x = fmaf(e2, v2.x, acc.x); acc.y = fmaf(e2, v2.y, acc.y);
            acc.z = fmaf(e2, v2.z, acc.z); acc.w = fmaf(e2, v2.w, acc.w);
            acc.x = fmaf(e3, v3.x, acc.x); acc.y = fmaf(e3, v3.y, acc.y);
            acc.z = fmaf(e3, v3.z, acc.z); acc.w = fmaf(e3, v3.w, acc.w);
            den += e0 + e1 + e2 + e3;
        }
        for (; j < nloc; j++) {
            int s = __shfl_sync(0xffffffffu, sj, j);
            float4 kv = k4[s * 32 + lane];
            float4 vv = v4[s * 32 + lane];
            float p = qv.x * kv.x + qv.y * kv.y + qv.z * kv.z + qv.w * kv.w;
            p += __shfl_xor_sync(0xffffffffu, p, 1);
            p += __shfl_xor_sync(0xffffffffu, p, 2);
            p += __shfl_xor_sync(0xffffffffu, p, 4);
            float ea = __expf(p * SC);
            acc.x = fmaf(ea, vv.x, acc.x);
            acc.y = fmaf(ea, vv.y, acc.y);
            acc.z = fmaf(ea, vv.z, acc.z);
            acc.w = fmaf(ea, vv.w, acc.w);
            den += ea;
        }
    }
    float inv = (den > 0.f) ? (1.0f / den) : 0.f;
    float4 o = ((float4*)out)[t * 32 + lane];
    o.x = fmaf(acc.x, inv, o.x);
    o.y = fmaf(acc.y, inv, o.y);
    o.z = fmaf(acc.z, inv, o.z);
    o.w = fmaf(acc.w, inv, o.w);
    ((float4*)out)[t * 32 + lane] = o;
}

// ---------------- launch -----------------------------------------------------
extern "C" void kernel_launch(void* const* d_in, const int* in_sizes, int n_in,
                              void* d_out, int out_size) {
    const float* x  = (const float*)d_in[0];
    const int*   ei = (const int*)d_in[1];
    const int* srcE = ei;        // edge_index[0]
    const int* tgtE = ei + EE;   // edge_index[1]
    const float* Wg = (const float*)d_in[2];
    const float* bg = (const float*)d_in[3];
    const float* Wq = (const float*)d_in[4];
    const float* bq = (const float*)d_in[5];
    const float* Wk = (const float*)d_in[6];
    const float* bk = (const float*)d_in[7];
    const float* Wv = (const float*)d_in[8];
    const float* bv = (const float*)d_in[9];
    const float* Wsk = (const float*)d_in[10];
    const float* bsk = (const float*)d_in[11];
    float* out = (float*)d_out;

    void *p_h0, *p_h, *p_q, *p_k, *p_v, *p_dinv;
    cudaGetSymbolAddress(&p_h0, g_h0);
    cudaGetSymbolAddress(&p_h,  g_h);
    cudaGetSymbolAddress(&p_q,  g_q);
    cudaGetSymbolAddress(&p_k,  g_k);
    cudaGetSymbolAddress(&p_v,  g_v);
    cudaGetSymbolAddress(&p_dinv, g_dinv);

    const int SMEM = (128 * 128 + 128 * 64) * (int)sizeof(float);   // 96KB
    cudaFuncSetAttribute(gemm4, cudaFuncAttributeMaxDynamicSharedMemorySize, SMEM);

    const int TB = 256;
    const int GBLK = (NN + 63) / 64;
    const int NODE_WARP_GRID = (NN * 32 + TB - 1) / TB;

    // CSR build first (dinv needed by the h0 GEMM epilogue)
    k_zero<<<(NN + TB - 1) / TB, TB>>>();                       // 1
    k_deg<<<(EE + TB - 1) / TB, TB>>>(tgtE);                    // 2
    k_scan<<<1, 1024>>>();                                      // 3 (+dinv)
    k_fill<<<(EE + TB - 1) / TB, TB>>>(srcE, tgtE);             // 4
    // h0' = dinv * (x @ W_gcn)
    gemm4<<<GBLK, TB, SMEM>>>(x, (const float*)p_dinv,          // 5
        Wg, nullptr, (float*)p_h0,
        nullptr, nullptr, nullptr,
        nullptr, nullptr, nullptr,
        nullptr, nullptr, nullptr, NN);
    // GCN aggregate + self loop + bias + ReLU (gather, no atomics)  -- launch #6 (profiled)
    k_gcn_agg<<<NODE_WARP_GRID, TB>>>(bg);                      // 6
    // q, k, v, skip projections in one kernel (skip writes straight to out)
    gemm4<<<GBLK, TB, SMEM>>>((const float*)p_h, nullptr,       // 7
        Wq, bq, (float*)p_q,
        Wk, bk, (float*)p_k,
        Wv, bv, (float*)p_v,
        Wsk, bsk, out, NN);
    // attention gather (no atomics)
    k_attn<<<NODE_WARP_GRID, TB>>>(out);                        // 8
}